// round 5
// baseline (speedup 1.0000x reference)
#include <cuda_runtime.h>
#include <cstdint>

#define T_STEPS 512
#define BATCH   64
#define DIN     128
#define DH      1024
#define DOUT    256
#define RANK    64
#define G_CTAS  128        // persistent CTAs in recurrence (<=148 SMs -> 1 wave)
#define J_COLS  8          // DH / G_CTAS

// ---------------- scratch (device globals: no allocations allowed) ----------
__device__ float    g_p[(T_STEPS + 1) * BATCH * RANK];   // p_seq[t][b][r]
__device__ float    g_part[G_CTAS * BATCH * RANK];       // per-CTA rank partials
__device__ unsigned g_bar1[T_STEPS + 1];
__device__ unsigned g_bar2[T_STEPS + 1];

// ---------------- init: reset barriers + p0 every launch (graph-safe) -------
__global__ void init_kernel() {
    int tid = blockIdx.x * blockDim.x + threadIdx.x;
    int stride = gridDim.x * blockDim.x;
    for (int i = tid; i < BATCH * RANK; i += stride) g_p[i] = 0.0f;
    for (int i = tid; i <= T_STEPS; i += stride) {
        g_bar1[i] = (i == 0) ? (unsigned)G_CTAS : 0u;
        g_bar2[i] = 0u;
    }
}

__device__ __forceinline__ void spin_acq(const unsigned* p, unsigned target) {
    unsigned v;
    do {
        asm volatile("ld.acquire.gpu.u32 %0, [%1];" : "=r"(v) : "l"(p) : "memory");
    } while (v < target);
}

// ---------------- generic C[m,n] = bias[n] + sum_k A[m,k]*B[n,k] ------------
// A: [M,K] row-major, B: [N,K] row-major (i.e. B^T GEMM). Tiles 64x64, BK=32.
// All dims divide exactly for both call sites (no bounds checks).
__global__ void __launch_bounds__(256) gemm_bt(const float* __restrict__ A,
                                               const float* __restrict__ Bm,
                                               const float* __restrict__ bias,
                                               float* __restrict__ C,
                                               int N, int K) {
    __shared__ float sA[32][68];   // transposed: sA[k][m]
    __shared__ float sB[32][68];   // transposed: sB[k][n]
    const int tid = threadIdx.x;
    const int m0 = blockIdx.x * 64;
    const int n0 = blockIdx.y * 64;
    const int tx = tid & 15;       // n micro-tile
    const int ty = tid >> 4;       // m micro-tile
    const int lrow = tid >> 2;     // 0..63 (load row)
    const int lkk  = (tid & 3) * 8;

    float acc[4][4];
#pragma unroll
    for (int i = 0; i < 4; i++)
#pragma unroll
        for (int j = 0; j < 4; j++) acc[i][j] = 0.0f;

    for (int k0 = 0; k0 < K; k0 += 32) {
        const float* ap = A + (size_t)(m0 + lrow) * K + k0 + lkk;
        const float* bp = Bm + (size_t)(n0 + lrow) * K + k0 + lkk;
        float4 a0 = *(const float4*)ap;
        float4 a1 = *(const float4*)(ap + 4);
        float4 b0 = *(const float4*)bp;
        float4 b1 = *(const float4*)(bp + 4);
        sA[lkk + 0][lrow] = a0.x; sA[lkk + 1][lrow] = a0.y;
        sA[lkk + 2][lrow] = a0.z; sA[lkk + 3][lrow] = a0.w;
        sA[lkk + 4][lrow] = a1.x; sA[lkk + 5][lrow] = a1.y;
        sA[lkk + 6][lrow] = a1.z; sA[lkk + 7][lrow] = a1.w;
        sB[lkk + 0][lrow] = b0.x; sB[lkk + 1][lrow] = b0.y;
        sB[lkk + 2][lrow] = b0.z; sB[lkk + 3][lrow] = b0.w;
        sB[lkk + 4][lrow] = b1.x; sB[lkk + 5][lrow] = b1.y;
        sB[lkk + 6][lrow] = b1.z; sB[lkk + 7][lrow] = b1.w;
        __syncthreads();
#pragma unroll
        for (int k = 0; k < 32; k++) {
            float4 av = *(const float4*)&sA[k][ty * 4];
            float4 bv = *(const float4*)&sB[k][tx * 4];
            float a[4] = {av.x, av.y, av.z, av.w};
            float b[4] = {bv.x, bv.y, bv.z, bv.w};
#pragma unroll
            for (int i = 0; i < 4; i++)
#pragma unroll
                for (int j = 0; j < 4; j++) acc[i][j] += a[i] * b[j];
        }
        __syncthreads();
    }

    float4 bias4 = *(const float4*)&bias[n0 + tx * 4];
    float bb[4] = {bias4.x, bias4.y, bias4.z, bias4.w};
#pragma unroll
    for (int i = 0; i < 4; i++) {
        float4 o;
        o.x = acc[i][0] + bb[0];
        o.y = acc[i][1] + bb[1];
        o.z = acc[i][2] + bb[2];
        o.w = acc[i][3] + bb[3];
        *(float4*)&C[(size_t)(m0 + ty * 4 + i) * N + n0 + tx * 4] = o;
    }
}

// ---------------- persistent recurrence kernel ------------------------------
// hidden holds c = zi + bh on entry; overwritten in place with h = relu(...).
// Each CTA owns 8 hidden columns [col0, col0+8). Per step:
//   phase ii : g[b][j] = c + sum_r p_prev[b][r]*U[col0+j][r];  h = relu(g)
//   phase iii-a: partial p: pp[b][r] = sum_j h[b][j]*V[r][col0+j] -> g_part
//   barrier 2; phase iii-b: each CTA reduces 32 of the 4096 p outputs over
//   the 128 partials and writes p_seq[t]; barrier 1 publishes p_t.
__global__ void __launch_bounds__(256, 1)
rnn_recur(const float* __restrict__ U, const float* __restrict__ V,
          float* __restrict__ hidden) {
    __shared__ float sP[64][68];   // p_prev[b][r] (padded: conflict-free)
    __shared__ float sU[8][68];    // U[col0+j][r]
    __shared__ float sV[64][12];   // V[r][col0+j] (stride 12: float4-aligned)
    __shared__ float sH[64][8];    // h slice
    __shared__ float sRed[32][9];  // iii-b cross-warp reduce

    const int tid = threadIdx.x;
    const int cta = blockIdx.x;
    const int col0 = cta * J_COLS;

    for (int i = tid; i < J_COLS * RANK; i += 256) {
        int j = i >> 6, r = i & 63;
        sU[j][r] = U[(size_t)(col0 + j) * RANK + r];
    }
    for (int i = tid; i < RANK * J_COLS; i += 256) {
        int r = i >> 3, j = i & 7;
        sV[r][j] = V[(size_t)r * DH + col0 + j];
    }
    __syncthreads();

    const int jj   = tid & 7;        // phase ii: column within slice
    const int brow = tid >> 3;       // phase ii: batch row (and +32)
    const int b3   = tid >> 2;       // phase iii-a: batch row 0..63
    const int rq   = tid & 3;        // phase iii-a: r-lane
    const int oL   = tid >> 3;       // phase iii-b: output 0..31
    const int kq   = tid & 7;        // phase iii-b: partial-group 0..7

    for (int t = 1; t <= T_STEPS; ++t) {
        // prefetch c for this step (independent of the barrier)
        float* cb = hidden + (size_t)(t - 1) * BATCH * DH + col0 + jj;
        float c0 = cb[(size_t)brow * DH];
        float c1 = cb[(size_t)(brow + 32) * DH];

        // wait for p_{t-1}
        if (tid == 0) spin_acq(&g_bar1[t - 1], G_CTAS);
        __syncthreads();

        // load p_prev into smem (4096 floats = 1024 float4)
        const float4* p4 = (const float4*)(g_p + (size_t)(t - 1) * BATCH * RANK);
#pragma unroll
        for (int i = 0; i < 4; ++i) {
            int idx = tid + i * 256;            // float4 index 0..1023
            float4 v = p4[idx];
            int b = idx >> 4;
            int r4 = (idx & 15) * 4;
            *(float4*)&sP[b][r4] = v;
        }
        __syncthreads();

        // ---- phase ii: g = p @ U^T + c ; h = relu(g) ----
        float g0 = c0, g1 = c1;
#pragma unroll
        for (int r = 0; r < RANK; r += 4) {
            float4 u  = *(const float4*)&sU[jj][r];
            float4 pa = *(const float4*)&sP[brow][r];
            float4 pb = *(const float4*)&sP[brow + 32][r];
            g0 += pa.x * u.x; g0 += pa.y * u.y; g0 += pa.z * u.z; g0 += pa.w * u.w;
            g1 += pb.x * u.x; g1 += pb.y * u.y; g1 += pb.z * u.z; g1 += pb.w * u.w;
        }
        float h0 = fmaxf(g0, 0.0f);
        float h1 = fmaxf(g1, 0.0f);
        cb[(size_t)brow * DH] = h0;
        cb[(size_t)(brow + 32) * DH] = h1;
        sH[brow][jj] = h0;
        sH[brow + 32][jj] = h1;
        __syncthreads();

        // ---- phase iii-a: partial p over this CTA's 8 columns ----
        float4 hA = *(const float4*)&sH[b3][0];
        float4 hB = *(const float4*)&sH[b3][4];
        float* partb = g_part + (size_t)cta * BATCH * RANK + b3 * RANK;
#pragma unroll
        for (int rr = 0; rr < 16; ++rr) {
            int r = rq + rr * 4;
            float4 vA = *(const float4*)&sV[r][0];
            float4 vB = *(const float4*)&sV[r][4];
            float acc = hA.x * vA.x + hA.y * vA.y + hA.z * vA.z + hA.w * vA.w
                      + hB.x * vB.x + hB.y * vB.y + hB.z * vB.z + hB.w * vB.w;
            partb[r] = acc;
        }
        __threadfence();
        __syncthreads();
        if (tid == 0) {
            atomicAdd(&g_bar2[t], 1u);
            spin_acq(&g_bar2[t], G_CTAS);
        }
        __syncthreads();

        // ---- phase iii-b: reduce 32 outputs over 128 partials ----
        {
            int o = cta * 32 + oL;
            float s = 0.0f;
            const float* gp = g_part + o;
#pragma unroll
            for (int k = kq * 16; k < kq * 16 + 16; ++k)
                s += gp[(size_t)k * BATCH * RANK];
            sRed[oL][kq] = s;
        }
        __syncthreads();
        if (tid < 32) {
            float tot = 0.0f;
#pragma unroll
            for (int k = 0; k < 8; ++k) tot += sRed[tid][k];
            g_p[(size_t)t * BATCH * RANK + cta * 32 + tid] = tot;
        }
        __threadfence();
        __syncthreads();
        if (tid == 0) atomicAdd(&g_bar1[t], 1u);
    }
}

// ---------------- launch -----------------------------------------------------
extern "C" void kernel_launch(void* const* d_in, const int* in_sizes, int n_in,
                              void* d_out, int out_size) {
    (void)in_sizes; (void)n_in; (void)out_size;
    const float* x  = (const float*)d_in[0];
    const float* Wi = (const float*)d_in[1];
    const float* U  = (const float*)d_in[2];
    const float* V  = (const float*)d_in[3];
    const float* bh = (const float*)d_in[4];
    const float* Wo = (const float*)d_in[5];
    const float* bo = (const float*)d_in[6];

    float* hidden = (float*)d_out;                                   // [T,B,DH]
    float* outp   = hidden + (size_t)T_STEPS * BATCH * DH;           // [T,B,DOUT]

    init_kernel<<<8, 256>>>();

    // c = x @ Wi^T + bh  -> written into the hidden region (consumed in place)
    dim3 gA(T_STEPS * BATCH / 64, DH / 64);
    gemm_bt<<<gA, 256>>>(x, Wi, bh, hidden, DH, DIN);

    // serial recurrence (persistent, 1 wave)
    rnn_recur<<<G_CTAS, 256>>>(U, V, hidden);

    // output = hidden @ Wo^T + bo
    dim3 gC(T_STEPS * BATCH / 64, DOUT / 64);
    gemm_bt<<<gC, 256>>>(hidden, Wo, bo, outp, DOUT, DH);
}

// round 7
// speedup vs baseline: 2.3953x; 2.3953x over previous
#include <cuda_runtime.h>
#include <cstdint>

#define T_STEPS 512
#define BATCH   64
#define DIN     128
#define DH      1024
#define DOUT    256
#define RANK    64

#define CL      4            // cluster size (CTAs per batch-pair)
#define COLS    256          // DH / CL columns per CTA
#define BGRP    2            // batch elements per cluster
// grid = 128 CTAs = 32 clusters * 4; one wave on 148 SMs

// ---------------- generic C[m,n] = bias[n] + sum_k A[m,k]*B[n,k] ------------
// A: [M,K] row-major, B: [N,K] row-major (B^T GEMM). Tiles 64x64, BK=32.
__global__ void __launch_bounds__(256) gemm_bt(const float* __restrict__ A,
                                               const float* __restrict__ Bm,
                                               const float* __restrict__ bias,
                                               float* __restrict__ C,
                                               int N, int K) {
    __shared__ float sA[32][68];
    __shared__ float sB[32][68];
    const int tid = threadIdx.x;
    const int m0 = blockIdx.x * 64;
    const int n0 = blockIdx.y * 64;
    const int tx = tid & 15;
    const int ty = tid >> 4;
    const int lrow = tid >> 2;
    const int lkk  = (tid & 3) * 8;

    float acc[4][4];
#pragma unroll
    for (int i = 0; i < 4; i++)
#pragma unroll
        for (int j = 0; j < 4; j++) acc[i][j] = 0.0f;

    for (int k0 = 0; k0 < K; k0 += 32) {
        const float* ap = A + (size_t)(m0 + lrow) * K + k0 + lkk;
        const float* bp = Bm + (size_t)(n0 + lrow) * K + k0 + lkk;
        float4 a0 = *(const float4*)ap;
        float4 a1 = *(const float4*)(ap + 4);
        float4 b0 = *(const float4*)bp;
        float4 b1 = *(const float4*)(bp + 4);
        sA[lkk + 0][lrow] = a0.x; sA[lkk + 1][lrow] = a0.y;
        sA[lkk + 2][lrow] = a0.z; sA[lkk + 3][lrow] = a0.w;
        sA[lkk + 4][lrow] = a1.x; sA[lkk + 5][lrow] = a1.y;
        sA[lkk + 6][lrow] = a1.z; sA[lkk + 7][lrow] = a1.w;
        sB[lkk + 0][lrow] = b0.x; sB[lkk + 1][lrow] = b0.y;
        sB[lkk + 2][lrow] = b0.z; sB[lkk + 3][lrow] = b0.w;
        sB[lkk + 4][lrow] = b1.x; sB[lkk + 5][lrow] = b1.y;
        sB[lkk + 6][lrow] = b1.z; sB[lkk + 7][lrow] = b1.w;
        __syncthreads();
#pragma unroll
        for (int k = 0; k < 32; k++) {
            float4 av = *(const float4*)&sA[k][ty * 4];
            float4 bv = *(const float4*)&sB[k][tx * 4];
            float a[4] = {av.x, av.y, av.z, av.w};
            float b[4] = {bv.x, bv.y, bv.z, bv.w};
#pragma unroll
            for (int i = 0; i < 4; i++)
#pragma unroll
                for (int j = 0; j < 4; j++) acc[i][j] += a[i] * b[j];
        }
        __syncthreads();
    }

    float4 bias4 = *(const float4*)&bias[n0 + tx * 4];
    float bb[4] = {bias4.x, bias4.y, bias4.z, bias4.w};
#pragma unroll
    for (int i = 0; i < 4; i++) {
        float4 o;
        o.x = acc[i][0] + bb[0];
        o.y = acc[i][1] + bb[1];
        o.z = acc[i][2] + bb[2];
        o.w = acc[i][3] + bb[3];
        *(float4*)&C[(size_t)(m0 + ty * 4 + i) * N + n0 + tx * 4] = o;
    }
}

// ---------------- clustered recurrence --------------------------------------
// Batches are independent. Cluster c owns batches {2c, 2c+1}; rank k owns
// columns [k*256, k*256+256). Weights live in REGISTERS:
//   u[64] = U[col][*]        (phase ii:  g = c + U * p,  h = relu(g))
//   v[64] = V[rr][q-chunk]   (phase iii: pp = V * h, partial over own cols)
// Rank-64 state p exchanged via DSMEM + one cluster barrier phase per step.
__device__ __forceinline__ uint32_t smem_u32(const void* p) {
    uint32_t a;
    asm("{ .reg .u64 t; cvta.to.shared.u64 t, %1; cvt.u32.u64 %0, t; }"
        : "=r"(a) : "l"(p));
    return a;
}

__global__ void __launch_bounds__(256, 1) __cluster_dims__(CL, 1, 1)
rnn_recur(const float* __restrict__ U, const float* __restrict__ V,
          float* __restrict__ hidden) {
    __shared__ float pbuf[2][CL][BGRP][RANK];   // double-buffered peer partials
    __shared__ float pcur[BGRP][RANK];          // reduced p_{t-1}
    __shared__ float sH[BGRP][COLS];            // h slice this step
    __shared__ float sTmp[CL][BGRP][RANK];      // q-group partials (phase iii)

    const int tid  = threadIdx.x;
    const int rank = blockIdx.x & (CL - 1);
    const int clus = blockIdx.x >> 2;
    const int b0   = clus * BGRP;
    const int colbase = rank * COLS;
    const int col  = colbase + tid;             // this thread's hidden column

    // phase-iii identity: rr = rank index 0..63, qq = 64-col chunk 0..3
    const int rr = tid & 63;
    const int qq = tid >> 6;

    // ---- persistent register weights ----
    float u[RANK];
#pragma unroll
    for (int r = 0; r < RANK; r += 4) {
        float4 t4 = *(const float4*)&U[(size_t)col * RANK + r];
        u[r] = t4.x; u[r + 1] = t4.y; u[r + 2] = t4.z; u[r + 3] = t4.w;
    }
    float v[64];
#pragma unroll
    for (int j = 0; j < 64; j += 4) {
        float4 t4 = *(const float4*)&V[(size_t)rr * DH + colbase + qq * 64 + j];
        v[j] = t4.x; v[j + 1] = t4.y; v[j + 2] = t4.z; v[j + 3] = t4.w;
    }

    // zero parity-0 buffer (p_0 = 0)
    for (int i = tid; i < CL * BGRP * RANK; i += 256)
        (&pbuf[0][0][0][0])[i] = 0.0f;

    // DSMEM peer addresses of pbuf (mapa once)
    uint32_t mybuf = smem_u32(&pbuf[0][0][0][0]);
    uint32_t peer[CL];
#pragma unroll
    for (int k = 0; k < CL; k++)
        asm("mapa.shared::cluster.u32 %0, %1, %2;"
            : "=r"(peer[k]) : "r"(mybuf), "r"(k));

    __syncthreads();

    for (int t = 1; t <= T_STEPS; ++t) {
        // prefetch c = zi + bh for this step BEFORE the cluster wait
        float* row = hidden + (size_t)(t - 1) * BATCH * DH;
        float c0 = row[(size_t)b0 * DH + col];
        float c1 = row[(size_t)(b0 + 1) * DH + col];

        if (t > 1)
            asm volatile("barrier.cluster.wait.aligned;" ::: "memory");

        // reduce the 4 rank-partials of p_{t-1}
        const int par = (t - 1) & 1;
        if (tid < BGRP * RANK) {
            int b = tid >> 6, r = tid & 63;
            pcur[b][r] = pbuf[par][0][b][r] + pbuf[par][1][b][r]
                       + pbuf[par][2][b][r] + pbuf[par][3][b][r];
        }
        __syncthreads();

        // ---- phase ii: g = c + u . p ; h = relu(g) ----
        float g0 = c0, g1 = c1;
        const float4* pa4 = (const float4*)pcur[0];
        const float4* pb4 = (const float4*)pcur[1];
#pragma unroll
        for (int r4 = 0; r4 < 16; ++r4) {
            float4 pa = pa4[r4];                 // broadcast LDS
            float4 pb = pb4[r4];
            g0 += u[4 * r4 + 0] * pa.x; g1 += u[4 * r4 + 0] * pb.x;
            g0 += u[4 * r4 + 1] * pa.y; g1 += u[4 * r4 + 1] * pb.y;
            g0 += u[4 * r4 + 2] * pa.z; g1 += u[4 * r4 + 2] * pb.z;
            g0 += u[4 * r4 + 3] * pa.w; g1 += u[4 * r4 + 3] * pb.w;
        }
        float h0 = fmaxf(g0, 0.0f);
        float h1 = fmaxf(g1, 0.0f);
        row[(size_t)b0 * DH + col] = h0;          // in-place: c -> h
        row[(size_t)(b0 + 1) * DH + col] = h1;
        sH[0][tid] = h0;
        sH[1][tid] = h1;
        __syncthreads();

        // ---- phase iii: pp[b][rr] partial over this thread's 64-col chunk --
        float a0 = 0.0f, a1 = 0.0f;
        const float4* h0q = (const float4*)&sH[0][qq * 64];  // warp-uniform
        const float4* h1q = (const float4*)&sH[1][qq * 64];
#pragma unroll
        for (int j4 = 0; j4 < 16; ++j4) {
            float4 ha = h0q[j4];                 // broadcast LDS
            float4 hb = h1q[j4];
            a0 += v[4 * j4 + 0] * ha.x; a1 += v[4 * j4 + 0] * hb.x;
            a0 += v[4 * j4 + 1] * ha.y; a1 += v[4 * j4 + 1] * hb.y;
            a0 += v[4 * j4 + 2] * ha.z; a1 += v[4 * j4 + 2] * hb.z;
            a0 += v[4 * j4 + 3] * ha.w; a1 += v[4 * j4 + 3] * hb.w;
        }
        sTmp[qq][0][rr] = a0;
        sTmp[qq][1][rr] = a1;
        __syncthreads();

        // ---- fold q-chunks + scatter to all 4 cluster CTAs via DSMEM -------
        const int wpar = t & 1;
        if (tid < BGRP * RANK) {
            int b = tid >> 6, r = tid & 63;
            float s = sTmp[0][b][r] + sTmp[1][b][r]
                    + sTmp[2][b][r] + sTmp[3][b][r];
            uint32_t off =
                (uint32_t)(((wpar * CL + rank) * BGRP + b) * RANK + r) * 4u;
#pragma unroll
            for (int k = 0; k < CL; k++)
                asm volatile("st.shared::cluster.f32 [%0], %1;"
                             :: "r"(peer[k] + off), "f"(s) : "memory");
        }
        // release: orders the DSMEM stores before peers' acquire-wait
        asm volatile("barrier.cluster.arrive.aligned;" ::: "memory");
    }
    // match final arrive; no CTA may exit while peers can still write our smem
    asm volatile("barrier.cluster.wait.aligned;" ::: "memory");
}

// ---------------- launch -----------------------------------------------------
extern "C" void kernel_launch(void* const* d_in, const int* in_sizes, int n_in,
                              void* d_out, int out_size) {
    (void)in_sizes; (void)n_in; (void)out_size;
    const float* x  = (const float*)d_in[0];
    const float* Wi = (const float*)d_in[1];
    const float* U  = (const float*)d_in[2];
    const float* V  = (const float*)d_in[3];
    const float* bh = (const float*)d_in[4];
    const float* Wo = (const float*)d_in[5];
    const float* bo = (const float*)d_in[6];

    float* hidden = (float*)d_out;                                   // [T,B,DH]
    float* outp   = hidden + (size_t)T_STEPS * BATCH * DH;           // [T,B,DOUT]

    // c = x @ Wi^T + bh  (written into hidden region, consumed in place)
    dim3 gA(T_STEPS * BATCH / 64, DH / 64);
    gemm_bt<<<gA, 256>>>(x, Wi, bh, hidden, DH, DIN);

    // serial recurrence: 32 clusters x 4 CTAs, DSMEM rank exchange
    rnn_recur<<<BATCH / BGRP * CL, 256>>>(U, V, hidden);

    // output = hidden @ Wo^T + bo
    dim3 gC(T_STEPS * BATCH / 64, DOUT / 64);
    gemm_bt<<<gC, 256>>>(hidden, Wo, bo, outp, DOUT, DH);
}

// round 8
// speedup vs baseline: 2.4754x; 1.0335x over previous
#include <cuda_runtime.h>
#include <cstdint>

#define T_STEPS 512
#define BATCH   64
#define DIN     128
#define DH      1024
#define DOUT    256
#define RANK    64

#define CL      4            // cluster size (CTAs per batch-pair)
#define COLS    256          // DH / CL columns per CTA
#define BGRP    2            // batch elements per cluster
// grid = 128 CTAs = 32 clusters * 4; one wave on 148 SMs

// ---------------- generic C[m,n] = bias[n] + sum_k A[m,k]*B[n,k] ------------
// A: [M,K] row-major, B: [N,K] row-major (B^T GEMM). Tiles 64x64, BK=32.
__global__ void __launch_bounds__(256) gemm_bt(const float* __restrict__ A,
                                               const float* __restrict__ Bm,
                                               const float* __restrict__ bias,
                                               float* __restrict__ C,
                                               int N, int K) {
    __shared__ float sA[32][68];
    __shared__ float sB[32][68];
    const int tid = threadIdx.x;
    const int m0 = blockIdx.x * 64;
    const int n0 = blockIdx.y * 64;
    const int tx = tid & 15;
    const int ty = tid >> 4;
    const int lrow = tid >> 2;
    const int lkk  = (tid & 3) * 8;

    float acc[4][4];
#pragma unroll
    for (int i = 0; i < 4; i++)
#pragma unroll
        for (int j = 0; j < 4; j++) acc[i][j] = 0.0f;

    for (int k0 = 0; k0 < K; k0 += 32) {
        const float* ap = A + (size_t)(m0 + lrow) * K + k0 + lkk;
        const float* bp = Bm + (size_t)(n0 + lrow) * K + k0 + lkk;
        float4 a0 = *(const float4*)ap;
        float4 a1 = *(const float4*)(ap + 4);
        float4 b0 = *(const float4*)bp;
        float4 b1 = *(const float4*)(bp + 4);
        sA[lkk + 0][lrow] = a0.x; sA[lkk + 1][lrow] = a0.y;
        sA[lkk + 2][lrow] = a0.z; sA[lkk + 3][lrow] = a0.w;
        sA[lkk + 4][lrow] = a1.x; sA[lkk + 5][lrow] = a1.y;
        sA[lkk + 6][lrow] = a1.z; sA[lkk + 7][lrow] = a1.w;
        sB[lkk + 0][lrow] = b0.x; sB[lkk + 1][lrow] = b0.y;
        sB[lkk + 2][lrow] = b0.z; sB[lkk + 3][lrow] = b0.w;
        sB[lkk + 4][lrow] = b1.x; sB[lkk + 5][lrow] = b1.y;
        sB[lkk + 6][lrow] = b1.z; sB[lkk + 7][lrow] = b1.w;
        __syncthreads();
#pragma unroll
        for (int k = 0; k < 32; k++) {
            float4 av = *(const float4*)&sA[k][ty * 4];
            float4 bv = *(const float4*)&sB[k][tx * 4];
            float a[4] = {av.x, av.y, av.z, av.w};
            float b[4] = {bv.x, bv.y, bv.z, bv.w};
#pragma unroll
            for (int i = 0; i < 4; i++)
#pragma unroll
                for (int j = 0; j < 4; j++) acc[i][j] += a[i] * b[j];
        }
        __syncthreads();
    }

    float4 bias4 = *(const float4*)&bias[n0 + tx * 4];
    float bb[4] = {bias4.x, bias4.y, bias4.z, bias4.w};
#pragma unroll
    for (int i = 0; i < 4; i++) {
        float4 o;
        o.x = acc[i][0] + bb[0];
        o.y = acc[i][1] + bb[1];
        o.z = acc[i][2] + bb[2];
        o.w = acc[i][3] + bb[3];
        *(float4*)&C[(size_t)(m0 + ty * 4 + i) * N + n0 + tx * 4] = o;
    }
}

// ---------------- clustered recurrence (mbarrier sync) -----------------------
__device__ __forceinline__ uint32_t smem_u32(const void* p) {
    uint32_t a;
    asm("{ .reg .u64 t; cvta.to.shared.u64 t, %1; cvt.u32.u64 %0, t; }"
        : "=r"(a) : "l"(p));
    return a;
}

// per-thread spin on local mbarrier parity (fast-path TRYWAIT)
__device__ __forceinline__ void mbar_wait(uint32_t mbar, uint32_t parity) {
    asm volatile(
        "{\n\t"
        ".reg .pred P;\n\t"
        "W%=:\n\t"
        "mbarrier.try_wait.parity.acquire.cta.shared::cta.b64 P, [%0], %1, 0x989680;\n\t"
        "@P bra D%=;\n\t"
        "bra W%=;\n\t"
        "D%=:\n\t"
        "}"
        :: "r"(mbar), "r"(parity) : "memory");
}

__global__ void __launch_bounds__(256, 1) __cluster_dims__(CL, 1, 1)
rnn_recur(const float* __restrict__ U, const float* __restrict__ V,
          float* __restrict__ hidden) {
    __shared__ float pbuf[2][CL][BGRP][RANK];   // parity-double-buffered partials
    __shared__ float pcur[BGRP][RANK];          // reduced p_{t-1}
    __shared__ float sH[BGRP][COLS];            // h slice this step
    __shared__ float sTmp[CL][BGRP][RANK];      // q-group partials (phase iii)
    __shared__ __align__(8) unsigned long long mbar;

    const int tid  = threadIdx.x;
    const int rank = blockIdx.x & (CL - 1);
    const int clus = blockIdx.x >> 2;
    const int b0   = clus * BGRP;
    const int colbase = rank * COLS;
    const int col  = colbase + tid;             // this thread's hidden column

    const int rr = tid & 63;                    // phase iii: rank index
    const int qq = tid >> 6;                    // phase iii: 64-col chunk

    // ---- persistent register weights ----
    float u[RANK];
#pragma unroll
    for (int r = 0; r < RANK; r += 4) {
        float4 t4 = *(const float4*)&U[(size_t)col * RANK + r];
        u[r] = t4.x; u[r + 1] = t4.y; u[r + 2] = t4.z; u[r + 3] = t4.w;
    }
    float v[64];
#pragma unroll
    for (int j = 0; j < 64; j += 4) {
        float4 t4 = *(const float4*)&V[(size_t)rr * DH + colbase + qq * 64 + j];
        v[j] = t4.x; v[j + 1] = t4.y; v[j + 2] = t4.z; v[j + 3] = t4.w;
    }

    // zero parity-0 buffer (p_0 = 0)
    for (int i = tid; i < CL * BGRP * RANK; i += 256)
        (&pbuf[0][0][0][0])[i] = 0.0f;

    const uint32_t mymbar = smem_u32(&mbar);
    if (tid == 0)
        asm volatile("mbarrier.init.shared.b64 [%0], %1;"
                     :: "r"(mymbar), "r"((unsigned)CL) : "memory");

    // DSMEM peer addresses (mapa once)
    uint32_t mybuf = smem_u32(&pbuf[0][0][0][0]);
    uint32_t peerbuf[CL], peerbar[CL];
#pragma unroll
    for (int k = 0; k < CL; k++) {
        asm("mapa.shared::cluster.u32 %0, %1, %2;"
            : "=r"(peerbuf[k]) : "r"(mybuf), "r"(k));
        asm("mapa.shared::cluster.u32 %0, %1, %2;"
            : "=r"(peerbar[k]) : "r"(mymbar), "r"(k));
    }
    __syncthreads();
    // all peers' mbarrier init + pbuf zero visible before any step traffic
    asm volatile("barrier.cluster.arrive.aligned;" ::: "memory");
    asm volatile("barrier.cluster.wait.aligned;" ::: "memory");

    // preload c for t = 1
    float c0 = hidden[(size_t)b0 * DH + col];
    float c1 = hidden[(size_t)(b0 + 1) * DH + col];

    for (int t = 1; t <= T_STEPS; ++t) {
        float* row = hidden + (size_t)(t - 1) * BATCH * DH;

        // wait for p_{t-1} partials (mbarrier parity; skew <= 1 phase)
        if (t >= 2) {
            mbar_wait(mymbar, (unsigned)(t & 1));
            if (tid == 0)
                asm volatile("fence.acq_rel.cluster;" ::: "memory");
            __syncthreads();   // cluster-scope acquire published to all threads
        }

        // reduce the 4 rank-partials of p_{t-1}
        const int par = (t - 1) & 1;
        if (tid < BGRP * RANK) {
            int b = tid >> 6, r = tid & 63;
            pcur[b][r] = pbuf[par][0][b][r] + pbuf[par][1][b][r]
                       + pbuf[par][2][b][r] + pbuf[par][3][b][r];
        }
        __syncthreads();

        // ---- phase ii: g = c + u . p ; h = relu(g) ----
        float g0 = c0, g1 = c1;
        const float4* pa4 = (const float4*)pcur[0];
        const float4* pb4 = (const float4*)pcur[1];
#pragma unroll
        for (int r4 = 0; r4 < 16; ++r4) {
            float4 pa = pa4[r4];                 // broadcast LDS
            float4 pb = pb4[r4];
            g0 += u[4 * r4 + 0] * pa.x; g1 += u[4 * r4 + 0] * pb.x;
            g0 += u[4 * r4 + 1] * pa.y; g1 += u[4 * r4 + 1] * pb.y;
            g0 += u[4 * r4 + 2] * pa.z; g1 += u[4 * r4 + 2] * pb.z;
            g0 += u[4 * r4 + 3] * pa.w; g1 += u[4 * r4 + 3] * pb.w;
        }
        float h0 = fmaxf(g0, 0.0f);
        float h1 = fmaxf(g1, 0.0f);
        row[(size_t)b0 * DH + col] = h0;          // in-place: c -> h
        row[(size_t)(b0 + 1) * DH + col] = h1;
        sH[0][tid] = h0;
        sH[1][tid] = h1;

        // prefetch c for step t+1 (row t untouched until step t+1 phase ii;
        // ~phase-iii + fold + wait of latency cover before consumption)
        if (t < T_STEPS) {
            const float* rowN = hidden + (size_t)t * BATCH * DH;
            c0 = rowN[(size_t)b0 * DH + col];
            c1 = rowN[(size_t)(b0 + 1) * DH + col];
        }
        __syncthreads();

        // ---- phase iii: pp[b][rr] partial over this thread's 64-col chunk --
        float a0 = 0.0f, a1 = 0.0f;
        const float4* h0q = (const float4*)&sH[0][qq * 64];  // warp-uniform
        const float4* h1q = (const float4*)&sH[1][qq * 64];
#pragma unroll
        for (int j4 = 0; j4 < 16; ++j4) {
            float4 ha = h0q[j4];                 // broadcast LDS
            float4 hb = h1q[j4];
            a0 += v[4 * j4 + 0] * ha.x; a1 += v[4 * j4 + 0] * hb.x;
            a0 += v[4 * j4 + 1] * ha.y; a1 += v[4 * j4 + 1] * hb.y;
            a0 += v[4 * j4 + 2] * ha.z; a1 += v[4 * j4 + 2] * hb.z;
            a0 += v[4 * j4 + 3] * ha.w; a1 += v[4 * j4 + 3] * hb.w;
        }
        sTmp[qq][0][rr] = a0;
        sTmp[qq][1][rr] = a1;
        __syncthreads();

        // ---- fold q-chunks + scatter to all 4 cluster CTAs via DSMEM -------
        const int wpar = t & 1;
        if (tid < BGRP * RANK) {
            int b = tid >> 6, r = tid & 63;
            float s = sTmp[0][b][r] + sTmp[1][b][r]
                    + sTmp[2][b][r] + sTmp[3][b][r];
            uint32_t off =
                (uint32_t)(((wpar * CL + rank) * BGRP + b) * RANK + r) * 4u;
#pragma unroll
            for (int k = 0; k < CL; k++)
                asm volatile("st.shared::cluster.f32 [%0], %1;"
                             :: "r"(peerbuf[k] + off), "f"(s) : "memory");
        }
        __syncthreads();       // all scatter stores issued before the release
        if (tid == 0) {
            asm volatile("fence.acq_rel.cluster;" ::: "memory");
#pragma unroll
            for (int k = 0; k < CL; k++)
                asm volatile("mbarrier.arrive.shared::cluster.b64 _, [%0];"
                             :: "r"(peerbar[k]) : "memory");
        }
    }

    // no CTA may exit while peers can still write our smem
    asm volatile("barrier.cluster.arrive.aligned;" ::: "memory");
    asm volatile("barrier.cluster.wait.aligned;" ::: "memory");
}

// ---------------- launch -----------------------------------------------------
extern "C" void kernel_launch(void* const* d_in, const int* in_sizes, int n_in,
                              void* d_out, int out_size) {
    (void)in_sizes; (void)n_in; (void)out_size;
    const float* x  = (const float*)d_in[0];
    const float* Wi = (const float*)d_in[1];
    const float* U  = (const float*)d_in[2];
    const float* V  = (const float*)d_in[3];
    const float* bh = (const float*)d_in[4];
    const float* Wo = (const float*)d_in[5];
    const float* bo = (const float*)d_in[6];

    float* hidden = (float*)d_out;                                   // [T,B,DH]
    float* outp   = hidden + (size_t)T_STEPS * BATCH * DH;           // [T,B,DOUT]

    // c = x @ Wi^T + bh  (written into hidden region, consumed in place)
    dim3 gA(T_STEPS * BATCH / 64, DH / 64);
    gemm_bt<<<gA, 256>>>(x, Wi, bh, hidden, DH, DIN);

    // serial recurrence: 32 clusters x 4 CTAs, DSMEM rank exchange
    rnn_recur<<<BATCH / BGRP * CL, 256>>>(U, V, hidden);

    // output = hidden @ Wo^T + bo
    dim3 gC(T_STEPS * BATCH / 64, DOUT / 64);
    gemm_bt<<<gC, 256>>>(hidden, Wo, bo, outp, DOUT, DH);
}